// round 13
// baseline (speedup 1.0000x reference)
#include <cuda_runtime.h>
#include <math.h>

#define Bb 8
#define Ss 4096
#define Dd 2048
#define N_ITEMS 8192
#define KTOP 64
#define SCHUNKS 64
#define SROWS (Ss / SCHUNKS)   // 64 rows per chunk

// ---- device scratch (static; every word rewritten every launch -> replay-safe) ----
__device__ float g_part[SCHUNKS][Bb][Dd];   // 4MB partial masked sums
__device__ float g_q[Bb][Dd];
__device__ float g_sims[Bb][N_ITEMS];
__device__ int   g_topi[Bb][KTOP];
__device__ float g_wfin[Bb][KTOP];
__device__ int   g_last[Bb];

// ---------------------------------------------------------------------------
// Kernel 1: copy x -> out (streaming) fused with masked partial column sums.
// grid (Dd/1024, SCHUNKS=64, Bb) = 1024 blocks x 256 threads. (R6-proven)
// ---------------------------------------------------------------------------
__global__ void __launch_bounds__(256) k_copy_reduce(
    const float* __restrict__ x, const unsigned char* __restrict__ mask,
    float* __restrict__ out) {
    const int b  = blockIdx.z;
    const int d0 = blockIdx.x * 1024 + threadIdx.x * 4;
    const int s0 = blockIdx.y * SROWS;
    const size_t base = (size_t)b * Ss * Dd + (size_t)s0 * Dd + d0;
    const float4* __restrict__ xp = (const float4*)(x + base);
    float4* __restrict__ op = (float4*)(out + base);
    const unsigned char* __restrict__ mp = mask + b * Ss + s0;

    float4 acc = make_float4(0.f, 0.f, 0.f, 0.f);
    #pragma unroll 8
    for (int s = 0; s < SROWS; s++) {
        float4 v = __ldcs(&xp[(size_t)s * (Dd / 4)]);
        __stcs(&op[(size_t)s * (Dd / 4)], v);
        float m = (float)mp[s];
        acc.x += v.x * m; acc.y += v.y * m; acc.z += v.z * m; acc.w += v.w * m;
    }
    *(float4*)&g_part[blockIdx.y][b][d0] = acc;
}

// ---------------------------------------------------------------------------
// Kernel 2: reduce partials, L2-normalize -> g_q. grid Bb x 512. (R6-proven)
// ---------------------------------------------------------------------------
__global__ void __launch_bounds__(512) k_qnorm() {
    const int b = blockIdx.x, t = threadIdx.x;
    const int d0 = t * 4;
    float4 acc = make_float4(0.f, 0.f, 0.f, 0.f);
    #pragma unroll 8
    for (int c = 0; c < SCHUNKS; c++) {
        float4 p = *(const float4*)&g_part[c][b][d0];
        acc.x += p.x; acc.y += p.y; acc.z += p.z; acc.w += p.w;
    }
    float ss = acc.x * acc.x + acc.y * acc.y + acc.z * acc.z + acc.w * acc.w;
    __shared__ float red[16];
    for (int o = 16; o > 0; o >>= 1) ss += __shfl_down_sync(0xffffffffu, ss, o);
    if ((t & 31) == 0) red[t >> 5] = ss;
    __syncthreads();
    __shared__ float s_inv;
    if (t == 0) {
        float tot = 0.f;
        #pragma unroll
        for (int w = 0; w < 16; w++) tot += red[w];
        s_inv = 1.0f / fmaxf(sqrtf(tot), 1e-12f);
    }
    __syncthreads();
    const float inv = s_inv;
    float4 q = make_float4(acc.x * inv, acc.y * inv, acc.z * inv, acc.w * inv);
    *(float4*)&g_q[b][d0] = q;
}

// ---------------------------------------------------------------------------
// Kernel 3: sims. 256 blocks x 256 threads; 4 keys per warp. (R6-proven exact)
// ---------------------------------------------------------------------------
__global__ void __launch_bounds__(256) k_sims(const float* __restrict__ keys) {
    extern __shared__ float sq[];  // [Bb][Dd] = 64KB
    for (int i = threadIdx.x; i < Bb * Dd / 4; i += blockDim.x)
        ((float4*)sq)[i] = ((const float4*)g_q)[i];
    __syncthreads();

    const int warp = threadIdx.x >> 5, lane = threadIdx.x & 31;
    const int n0 = (blockIdx.x * 8 + warp) * 4;

    const float4* __restrict__ k0 = (const float4*)(keys + (size_t)(n0 + 0) * Dd);
    const float4* __restrict__ k1 = (const float4*)(keys + (size_t)(n0 + 1) * Dd);
    const float4* __restrict__ k2 = (const float4*)(keys + (size_t)(n0 + 2) * Dd);
    const float4* __restrict__ k3 = (const float4*)(keys + (size_t)(n0 + 3) * Dd);

    float dot[4][Bb];
    float ssq[4] = {0.f, 0.f, 0.f, 0.f};
    #pragma unroll
    for (int j = 0; j < 4; j++)
        #pragma unroll
        for (int bb = 0; bb < Bb; bb++) dot[j][bb] = 0.f;

    #pragma unroll 2
    for (int i = lane; i < Dd / 4; i += 32) {
        float4 kv[4];
        kv[0] = __ldcs(&k0[i]); kv[1] = __ldcs(&k1[i]);
        kv[2] = __ldcs(&k2[i]); kv[3] = __ldcs(&k3[i]);
        #pragma unroll
        for (int j = 0; j < 4; j++)
            ssq[j] += kv[j].x * kv[j].x + kv[j].y * kv[j].y
                    + kv[j].z * kv[j].z + kv[j].w * kv[j].w;
        #pragma unroll
        for (int bb = 0; bb < Bb; bb++) {
            float4 qv = ((const float4*)(sq + bb * Dd))[i];
            #pragma unroll
            for (int j = 0; j < 4; j++)
                dot[j][bb] += kv[j].x * qv.x + kv[j].y * qv.y
                            + kv[j].z * qv.z + kv[j].w * qv.w;
        }
    }
    #pragma unroll
    for (int o = 16; o > 0; o >>= 1) {
        #pragma unroll
        for (int j = 0; j < 4; j++) {
            ssq[j] += __shfl_down_sync(0xffffffffu, ssq[j], o);
            #pragma unroll
            for (int bb = 0; bb < Bb; bb++)
                dot[j][bb] += __shfl_down_sync(0xffffffffu, dot[j][bb], o);
        }
    }
    if (lane == 0) {
        #pragma unroll
        for (int j = 0; j < 4; j++) {
            float inv = 1.0f / fmaxf(sqrtf(ssq[j]), 1e-12f);
            #pragma unroll
            for (int bb = 0; bb < Bb; bb++) g_sims[bb][n0 + j] = dot[j][bb] * inv;
        }
    }
}

// ---------------------------------------------------------------------------
// Kernel 4: radix select; level-3 histogram uses warp-aggregated atomics
// (__match_any_sync) because clustered sims cause within-warp same-address
// lane serialization in ATOMS. grid Bb x 1024.
// ---------------------------------------------------------------------------
__global__ void __launch_bounds__(1024) k_select(const unsigned char* __restrict__ mask) {
    const int b = blockIdx.x, t = threadIdx.x;
    const int w = t >> 5, lane = t & 31;

    __shared__ int      s_hist[256];
    __shared__ int      s_B, s_carried;
    __shared__ int      s_redc[32];
    __shared__ int      s_topi[KTOP];
    __shared__ int      s_eqi[KTOP];
    __shared__ int      s_ngt, s_neq;
    __shared__ unsigned s_umax;
    __shared__ float    s_w[KTOP];

    int cnt = 0;
    #pragma unroll
    for (int i = 0; i < 4; i++) cnt += (int)mask[b * Ss + t + i * 1024];
    for (int o = 16; o > 0; o >>= 1) cnt += __shfl_down_sync(0xffffffffu, cnt, o);
    if (lane == 0) s_redc[w] = cnt;

    unsigned u[8];
    #pragma unroll
    for (int j = 0; j < 8; j++) {
        unsigned bits = __float_as_uint(g_sims[b][t + j * 1024]);
        u[j] = bits ^ (unsigned)(((int)bits >> 31) | 0x80000000);
    }

    unsigned prefix = 0;
    int carried = 0;

    // ---- level 3: all 8192 items, warp-aggregated atomics ----
    {
        if (t < 256) s_hist[t] = 0;
        __syncthreads();
        #pragma unroll
        for (int j = 0; j < 8; j++) {
            const int bin = (int)(u[j] >> 24);
            unsigned grp = __match_any_sync(0xffffffffu, bin);
            int leader = __ffs(grp) - 1;
            if (lane == leader) atomicAdd(&s_hist[bin], __popc(grp));
        }
        __syncthreads();
        if (t < 32) {
            int h[8], gs = 0;
            #pragma unroll
            for (int j = 0; j < 8; j++) { h[j] = s_hist[lane * 8 + j]; gs += h[j]; }
            int suf = gs;
            #pragma unroll
            for (int o = 1; o < 32; o <<= 1) {
                int v = __shfl_down_sync(0xffffffffu, suf, o);
                if (lane < 32 - o) suf += v;
            }
            int cum = suf - gs;
            #pragma unroll
            for (int j = 7; j >= 0; j--) {
                int before = cum;
                cum += h[j];
                if (before < KTOP && cum >= KTOP) { s_B = lane * 8 + j; s_carried = before; }
            }
        }
        __syncthreads();
        prefix = (unsigned)s_B;
        carried = s_carried;
        __syncthreads();
    }

    // ---- levels 2..0: few surviving items, plain atomics ----
    for (int l = 2; l >= 0; l--) {
        if (t < 256) s_hist[t] = 0;
        __syncthreads();
        #pragma unroll
        for (int j = 0; j < 8; j++) {
            unsigned hi = u[j] >> ((l + 1) * 8);
            if (hi == prefix)
                atomicAdd(&s_hist[(u[j] >> (l * 8)) & 255], 1);
        }
        __syncthreads();
        if (t < 32) {
            int h[8], gs = 0;
            #pragma unroll
            for (int j = 0; j < 8; j++) { h[j] = s_hist[lane * 8 + j]; gs += h[j]; }
            int suf = gs;
            #pragma unroll
            for (int o = 1; o < 32; o <<= 1) {
                int v = __shfl_down_sync(0xffffffffu, suf, o);
                if (lane < 32 - o) suf += v;
            }
            int cum = carried + (suf - gs);
            #pragma unroll
            for (int j = 7; j >= 0; j--) {
                int before = cum;
                cum += h[j];
                if (before < KTOP && cum >= KTOP) { s_B = lane * 8 + j; s_carried = before; }
            }
        }
        __syncthreads();
        prefix = (prefix << 8) | (unsigned)s_B;
        carried = s_carried;
        __syncthreads();
    }
    const unsigned p = prefix;

    if (t == 0) { s_ngt = 0; s_neq = 0; s_umax = p; }
    __syncthreads();

    unsigned local_max = 0;
    #pragma unroll
    for (int j = 0; j < 8; j++) {
        if (u[j] > p) {
            int pos = atomicAdd(&s_ngt, 1);
            s_topi[pos] = t + j * 1024;
            if (u[j] > local_max) local_max = u[j];
        } else if (u[j] == p) {
            int pos = atomicAdd(&s_neq, 1);
            if (pos < KTOP) s_eqi[pos] = t + j * 1024;
        }
    }
    if (local_max > p) atomicMax(&s_umax, local_max);
    __syncthreads();
    const int ngt = s_ngt;
    if (t < KTOP - ngt) s_topi[ngt + t] = s_eqi[t];

    const unsigned umax = s_umax;
    const unsigned mb = (umax >> 31) ? (umax ^ 0x80000000u) : ~umax;
    const float fmaxv = __uint_as_float(mb);
    __syncthreads();

    if (t < KTOP) s_w[t] = __expf((g_sims[b][s_topi[t]] - fmaxv) * (1.0f / 0.03f));
    __syncthreads();
    if (t == 0) {
        float sum = 0.f;
        #pragma unroll
        for (int k = 0; k < KTOP; k++) sum += s_w[k];
        float gate = 1.0f / (1.0f + __expf(-(fmaxv - 0.85f) * 40.0f));
        float scale = 16.0f * gate / sum;
        int tot = 0;
        #pragma unroll
        for (int ww = 0; ww < 32; ww++) tot += s_redc[ww];
        g_last[b] = max(tot, 1) - 1;
        s_redc[0] = __float_as_int(scale);
    }
    __syncthreads();
    if (t < KTOP) {
        g_topi[b][t] = s_topi[t];
        g_wfin[b][t] = s_w[t] * __int_as_float(s_redc[0]);
    }
}

// ---------------------------------------------------------------------------
// Kernel 5: gather weighted values, add delta to out[b, last, :].
// grid (8 col-chunks, Bb) x 256 threads. (R6-proven)
// ---------------------------------------------------------------------------
__global__ void __launch_bounds__(256) k_gather(
    const float* __restrict__ values, float* __restrict__ out) {
    const int b = blockIdx.y, c = blockIdx.x, t = threadIdx.x;
    __shared__ float sw[KTOP];
    __shared__ int   si[KTOP];
    __shared__ float4 sacc[256];

    if (t < KTOP) { sw[t] = g_wfin[b][t]; si[t] = g_topi[b][t]; }
    __syncthreads();

    const int kg = t >> 6;
    const int col = t & 63;
    const int doff = c * 256 + col * 4;

    float4 acc = make_float4(0.f, 0.f, 0.f, 0.f);
    #pragma unroll
    for (int kk = 0; kk < 16; kk++) {
        const int k = kg * 16 + kk;
        const float4 vv = __ldg((const float4*)(values + (size_t)si[k] * Dd + doff));
        const float wk = sw[k];
        acc.x += wk * vv.x; acc.y += wk * vv.y;
        acc.z += wk * vv.z; acc.w += wk * vv.w;
    }
    sacc[t] = acc;
    __syncthreads();
    if (t < 64) {
        float4 a0 = sacc[t], a1 = sacc[t + 64], a2 = sacc[t + 128], a3 = sacc[t + 192];
        a0.x += a1.x + a2.x + a3.x;
        a0.y += a1.y + a2.y + a3.y;
        a0.z += a1.z + a2.z + a3.z;
        a0.w += a1.w + a2.w + a3.w;
        float* op = out + (size_t)b * Ss * Dd + (size_t)g_last[b] * Dd + c * 256 + t * 4;
        float4 cur = *(float4*)op;
        cur.x += a0.x; cur.y += a0.y; cur.z += a0.z; cur.w += a0.w;
        *(float4*)op = cur;
    }
}

extern "C" void kernel_launch(void* const* d_in, const int* in_sizes, int n_in,
                              void* d_out, int out_size) {
    const float*         x    = (const float*)d_in[0];
    const unsigned char* mask = (const unsigned char*)d_in[1];
    const float*         keys = (const float*)d_in[2];
    const float*         vals = (const float*)d_in[3];
    float* out = (float*)d_out;

    cudaFuncSetAttribute(k_sims, cudaFuncAttributeMaxDynamicSharedMemorySize,
                         Bb * Dd * (int)sizeof(float));

    k_copy_reduce<<<dim3(Dd / 1024, SCHUNKS, Bb), 256>>>(x, mask, out);
    k_qnorm<<<Bb, 512>>>();
    k_sims<<<256, 256, Bb * Dd * sizeof(float)>>>(keys);
    k_select<<<Bb, 1024>>>(mask);
    k_gather<<<dim3(8, Bb), 256>>>(vals, out);
}

// round 14
// speedup vs baseline: 1.0398x; 1.0398x over previous
#include <cuda_runtime.h>
#include <math.h>

#define Bb 8
#define Ss 4096
#define Dd 2048
#define N_ITEMS 8192
#define KTOP 64
#define SCHUNKS 64
#define SROWS (Ss / SCHUNKS)   // 64 rows per chunk

// ---- device scratch (static; every word rewritten every launch -> replay-safe) ----
__device__ float g_part[SCHUNKS][Bb][Dd];   // 4MB partial masked sums
__device__ float g_q[Bb][Dd];
__device__ float g_sims[Bb][N_ITEMS];

// ---------------------------------------------------------------------------
// Kernel 1: copy x -> out (streaming) fused with masked partial column sums.
// grid (Dd/1024, SCHUNKS=64, Bb) = 1024 blocks x 256 threads. (R6-proven)
// ---------------------------------------------------------------------------
__global__ void __launch_bounds__(256) k_copy_reduce(
    const float* __restrict__ x, const unsigned char* __restrict__ mask,
    float* __restrict__ out) {
    const int b  = blockIdx.z;
    const int d0 = blockIdx.x * 1024 + threadIdx.x * 4;
    const int s0 = blockIdx.y * SROWS;
    const size_t base = (size_t)b * Ss * Dd + (size_t)s0 * Dd + d0;
    const float4* __restrict__ xp = (const float4*)(x + base);
    float4* __restrict__ op = (float4*)(out + base);
    const unsigned char* __restrict__ mp = mask + b * Ss + s0;

    float4 acc = make_float4(0.f, 0.f, 0.f, 0.f);
    #pragma unroll 8
    for (int s = 0; s < SROWS; s++) {
        float4 v = __ldcs(&xp[(size_t)s * (Dd / 4)]);
        __stcs(&op[(size_t)s * (Dd / 4)], v);
        float m = (float)mp[s];
        acc.x += v.x * m; acc.y += v.y * m; acc.z += v.z * m; acc.w += v.w * m;
    }
    *(float4*)&g_part[blockIdx.y][b][d0] = acc;
}

// ---------------------------------------------------------------------------
// Kernel 2: reduce partials, L2-normalize -> g_q. grid Bb x 512. (R6-proven)
// ---------------------------------------------------------------------------
__global__ void __launch_bounds__(512) k_qnorm() {
    const int b = blockIdx.x, t = threadIdx.x;
    const int d0 = t * 4;
    float4 acc = make_float4(0.f, 0.f, 0.f, 0.f);
    #pragma unroll 8
    for (int c = 0; c < SCHUNKS; c++) {
        float4 p = *(const float4*)&g_part[c][b][d0];
        acc.x += p.x; acc.y += p.y; acc.z += p.z; acc.w += p.w;
    }
    float ss = acc.x * acc.x + acc.y * acc.y + acc.z * acc.z + acc.w * acc.w;
    __shared__ float red[16];
    for (int o = 16; o > 0; o >>= 1) ss += __shfl_down_sync(0xffffffffu, ss, o);
    if ((t & 31) == 0) red[t >> 5] = ss;
    __syncthreads();
    __shared__ float s_inv;
    if (t == 0) {
        float tot = 0.f;
        #pragma unroll
        for (int w = 0; w < 16; w++) tot += red[w];
        s_inv = 1.0f / fmaxf(sqrtf(tot), 1e-12f);
    }
    __syncthreads();
    const float inv = s_inv;
    float4 q = make_float4(acc.x * inv, acc.y * inv, acc.z * inv, acc.w * inv);
    *(float4*)&g_q[b][d0] = q;
}

// ---------------------------------------------------------------------------
// Kernel 3: sims. 256 blocks x 256 threads; 4 keys per warp. (R6-proven exact)
// ---------------------------------------------------------------------------
__global__ void __launch_bounds__(256) k_sims(const float* __restrict__ keys) {
    extern __shared__ float sq[];  // [Bb][Dd] = 64KB
    for (int i = threadIdx.x; i < Bb * Dd / 4; i += blockDim.x)
        ((float4*)sq)[i] = ((const float4*)g_q)[i];
    __syncthreads();

    const int warp = threadIdx.x >> 5, lane = threadIdx.x & 31;
    const int n0 = (blockIdx.x * 8 + warp) * 4;

    const float4* __restrict__ k0 = (const float4*)(keys + (size_t)(n0 + 0) * Dd);
    const float4* __restrict__ k1 = (const float4*)(keys + (size_t)(n0 + 1) * Dd);
    const float4* __restrict__ k2 = (const float4*)(keys + (size_t)(n0 + 2) * Dd);
    const float4* __restrict__ k3 = (const float4*)(keys + (size_t)(n0 + 3) * Dd);

    float dot[4][Bb];
    float ssq[4] = {0.f, 0.f, 0.f, 0.f};
    #pragma unroll
    for (int j = 0; j < 4; j++)
        #pragma unroll
        for (int bb = 0; bb < Bb; bb++) dot[j][bb] = 0.f;

    #pragma unroll 2
    for (int i = lane; i < Dd / 4; i += 32) {
        float4 kv[4];
        kv[0] = __ldcs(&k0[i]); kv[1] = __ldcs(&k1[i]);
        kv[2] = __ldcs(&k2[i]); kv[3] = __ldcs(&k3[i]);
        #pragma unroll
        for (int j = 0; j < 4; j++)
            ssq[j] += kv[j].x * kv[j].x + kv[j].y * kv[j].y
                    + kv[j].z * kv[j].z + kv[j].w * kv[j].w;
        #pragma unroll
        for (int bb = 0; bb < Bb; bb++) {
            float4 qv = ((const float4*)(sq + bb * Dd))[i];
            #pragma unroll
            for (int j = 0; j < 4; j++)
                dot[j][bb] += kv[j].x * qv.x + kv[j].y * qv.y
                            + kv[j].z * qv.z + kv[j].w * qv.w;
        }
    }
    #pragma unroll
    for (int o = 16; o > 0; o >>= 1) {
        #pragma unroll
        for (int j = 0; j < 4; j++) {
            ssq[j] += __shfl_down_sync(0xffffffffu, ssq[j], o);
            #pragma unroll
            for (int bb = 0; bb < Bb; bb++)
                dot[j][bb] += __shfl_down_sync(0xffffffffu, dot[j][bb], o);
        }
    }
    if (lane == 0) {
        #pragma unroll
        for (int j = 0; j < 4; j++) {
            float inv = 1.0f / fmaxf(sqrtf(ssq[j]), 1e-12f);
            #pragma unroll
            for (int bb = 0; bb < Bb; bb++) g_sims[bb][n0 + j] = dot[j][bb] * inv;
        }
    }
}

// ---------------------------------------------------------------------------
// Kernel 4: fused select+gather. grid (8 col-chunks, Bb) x 1024 threads.
// Each of the 8 blocks per batch REDUNDANTLY runs the R6 radix select (sims
// are L2-resident; blocks run concurrently so redundancy costs ~nothing),
// then gathers its own 256-float column chunk. Top-64 is a set: per-block
// atomic ordering differences don't change the summed result.
// ---------------------------------------------------------------------------
__global__ void __launch_bounds__(1024) k_select_gather(
    const unsigned char* __restrict__ mask,
    const float* __restrict__ values, float* __restrict__ out) {
    const int c = blockIdx.x, b = blockIdx.y, t = threadIdx.x;
    const int w = t >> 5, lane = t & 31;

    __shared__ int      s_hist[256];
    __shared__ int      s_B, s_carried;
    __shared__ int      s_redc[32];
    __shared__ int      s_topi[KTOP];
    __shared__ int      s_eqi[KTOP];
    __shared__ int      s_ngt, s_neq;
    __shared__ unsigned s_umax;
    __shared__ float    s_w[KTOP];
    __shared__ int      s_last;
    __shared__ float4   sacc[16][64];   // 16KB gather partials

    // ---- mask count (last valid index) ----
    int cnt = 0;
    #pragma unroll
    for (int i = 0; i < 4; i++) cnt += (int)mask[b * Ss + t + i * 1024];
    for (int o = 16; o > 0; o >>= 1) cnt += __shfl_down_sync(0xffffffffu, cnt, o);
    if (lane == 0) s_redc[w] = cnt;

    // ---- load sims -> order-preserving uint ----
    unsigned u[8];
    #pragma unroll
    for (int j = 0; j < 8; j++) {
        unsigned bits = __float_as_uint(g_sims[b][t + j * 1024]);
        u[j] = bits ^ (unsigned)(((int)bits >> 31) | 0x80000000);
    }

    // ---- 4-level radix: find exact 64th-largest u (R6-proven) ----
    unsigned prefix = 0;
    int carried = 0;
    #pragma unroll
    for (int l = 3; l >= 0; l--) {
        if (t < 256) s_hist[t] = 0;
        __syncthreads();
        #pragma unroll
        for (int j = 0; j < 8; j++) {
            unsigned hi = (l == 3) ? 0u : (u[j] >> ((l + 1) * 8));
            if (hi == prefix)
                atomicAdd(&s_hist[(u[j] >> (l * 8)) & 255], 1);
        }
        __syncthreads();
        if (t < 32) {
            int h[8], gs = 0;
            #pragma unroll
            for (int j = 0; j < 8; j++) { h[j] = s_hist[lane * 8 + j]; gs += h[j]; }
            int suf = gs;
            #pragma unroll
            for (int o = 1; o < 32; o <<= 1) {
                int v = __shfl_down_sync(0xffffffffu, suf, o);
                if (lane < 32 - o) suf += v;
            }
            int cum = carried + (suf - gs);
            #pragma unroll
            for (int j = 7; j >= 0; j--) {
                int before = cum;
                cum += h[j];
                if (before < KTOP && cum >= KTOP) { s_B = lane * 8 + j; s_carried = before; }
            }
        }
        __syncthreads();
        prefix = (prefix << 8) | (unsigned)s_B;
        carried = s_carried;
        __syncthreads();
    }
    const unsigned p = prefix;

    if (t == 0) { s_ngt = 0; s_neq = 0; s_umax = p; }
    __syncthreads();

    // ---- collect: all u > p, then fill with u == p ----
    unsigned local_max = 0;
    #pragma unroll
    for (int j = 0; j < 8; j++) {
        if (u[j] > p) {
            int pos = atomicAdd(&s_ngt, 1);
            s_topi[pos] = t + j * 1024;
            if (u[j] > local_max) local_max = u[j];
        } else if (u[j] == p) {
            int pos = atomicAdd(&s_neq, 1);
            if (pos < KTOP) s_eqi[pos] = t + j * 1024;
        }
    }
    if (local_max > p) atomicMax(&s_umax, local_max);
    __syncthreads();
    const int ngt = s_ngt;
    if (t < KTOP - ngt) s_topi[ngt + t] = s_eqi[t];

    const unsigned umax = s_umax;
    const unsigned mb = (umax >> 31) ? (umax ^ 0x80000000u) : ~umax;
    const float fmaxv = __uint_as_float(mb);
    __syncthreads();

    if (t < KTOP) s_w[t] = __expf((g_sims[b][s_topi[t]] - fmaxv) * (1.0f / 0.03f));
    __syncthreads();
    if (t == 0) {
        float sum = 0.f;
        #pragma unroll
        for (int k = 0; k < KTOP; k++) sum += s_w[k];
        float gate = 1.0f / (1.0f + __expf(-(fmaxv - 0.85f) * 40.0f));
        s_hist[0] = __float_as_int(16.0f * gate / sum);   // stash scale
        int tot = 0;
        #pragma unroll
        for (int ww = 0; ww < 32; ww++) tot += s_redc[ww];
        s_last = max(tot, 1) - 1;
    }
    __syncthreads();
    const float scale = __int_as_float(s_hist[0]);
    if (t < KTOP) s_w[t] *= scale;
    __syncthreads();

    // ---- gather this block's 256-float chunk: 16 k-groups x 64 cols ----
    const int col = t & 63;        // float4 column within chunk
    const int grp = t >> 6;        // 0..15, 4 k's each
    const int doff = c * 256 + col * 4;

    float4 acc = make_float4(0.f, 0.f, 0.f, 0.f);
    #pragma unroll
    for (int kk = 0; kk < 4; kk++) {
        const int k = grp * 4 + kk;
        const float4 vv = __ldg((const float4*)(values + (size_t)s_topi[k] * Dd + doff));
        const float wk = s_w[k];
        acc.x += wk * vv.x; acc.y += wk * vv.y;
        acc.z += wk * vv.z; acc.w += wk * vv.w;
    }
    sacc[grp][col] = acc;
    __syncthreads();
    if (t < 64) {
        float4 a = sacc[0][t];
        #pragma unroll
        for (int g = 1; g < 16; g++) {
            float4 v = sacc[g][t];
            a.x += v.x; a.y += v.y; a.z += v.z; a.w += v.w;
        }
        float* op = out + (size_t)b * Ss * Dd + (size_t)s_last * Dd + c * 256 + t * 4;
        float4 cur = *(float4*)op;
        cur.x += a.x; cur.y += a.y; cur.z += a.z; cur.w += a.w;
        *(float4*)op = cur;
    }
}

extern "C" void kernel_launch(void* const* d_in, const int* in_sizes, int n_in,
                              void* d_out, int out_size) {
    const float*         x    = (const float*)d_in[0];
    const unsigned char* mask = (const unsigned char*)d_in[1];
    const float*         keys = (const float*)d_in[2];
    const float*         vals = (const float*)d_in[3];
    float* out = (float*)d_out;

    cudaFuncSetAttribute(k_sims, cudaFuncAttributeMaxDynamicSharedMemorySize,
                         Bb * Dd * (int)sizeof(float));

    k_copy_reduce<<<dim3(Dd / 1024, SCHUNKS, Bb), 256>>>(x, mask, out);
    k_qnorm<<<Bb, 512>>>();
    k_sims<<<256, 256, Bb * Dd * sizeof(float)>>>(keys);
    k_select_gather<<<dim3(8, Bb), 1024>>>(mask, vals, out);
}

// round 15
// speedup vs baseline: 1.0518x; 1.0115x over previous
#include <cuda_runtime.h>
#include <math.h>

#define Bb 8
#define Ss 4096
#define Dd 2048
#define N_ITEMS 8192
#define KTOP 64
#define SCHUNKS 64
#define SROWS (Ss / SCHUNKS)   // 64 rows per chunk

// ---- device scratch (static; every word rewritten every launch -> replay-safe) ----
__device__ float g_part[SCHUNKS][Bb][Dd];   // 4MB partial masked sums
__device__ float g_q[Bb][Dd];
__device__ float g_sims[Bb][N_ITEMS];

// ---------------------------------------------------------------------------
// Kernel 1: copy x -> out (streaming) fused with masked partial column sums.
// grid (Dd/1024, SCHUNKS=64, Bb) = 1024 blocks x 256 threads. (R6-proven)
// ---------------------------------------------------------------------------
__global__ void __launch_bounds__(256) k_copy_reduce(
    const float* __restrict__ x, const unsigned char* __restrict__ mask,
    float* __restrict__ out) {
    const int b  = blockIdx.z;
    const int d0 = blockIdx.x * 1024 + threadIdx.x * 4;
    const int s0 = blockIdx.y * SROWS;
    const size_t base = (size_t)b * Ss * Dd + (size_t)s0 * Dd + d0;
    const float4* __restrict__ xp = (const float4*)(x + base);
    float4* __restrict__ op = (float4*)(out + base);
    const unsigned char* __restrict__ mp = mask + b * Ss + s0;

    float4 acc = make_float4(0.f, 0.f, 0.f, 0.f);
    #pragma unroll 8
    for (int s = 0; s < SROWS; s++) {
        float4 v = __ldcs(&xp[(size_t)s * (Dd / 4)]);
        __stcs(&op[(size_t)s * (Dd / 4)], v);
        float m = (float)mp[s];
        acc.x += v.x * m; acc.y += v.y * m; acc.z += v.z * m; acc.w += v.w * m;
    }
    *(float4*)&g_part[blockIdx.y][b][d0] = acc;
}

// ---------------------------------------------------------------------------
// Kernel 2: reduce partials, L2-normalize -> g_q. grid Bb x 512. (R6-proven)
// ---------------------------------------------------------------------------
__global__ void __launch_bounds__(512) k_qnorm() {
    const int b = blockIdx.x, t = threadIdx.x;
    const int d0 = t * 4;
    float4 acc = make_float4(0.f, 0.f, 0.f, 0.f);
    #pragma unroll 8
    for (int c = 0; c < SCHUNKS; c++) {
        float4 p = *(const float4*)&g_part[c][b][d0];
        acc.x += p.x; acc.y += p.y; acc.z += p.z; acc.w += p.w;
    }
    float ss = acc.x * acc.x + acc.y * acc.y + acc.z * acc.z + acc.w * acc.w;
    __shared__ float red[16];
    for (int o = 16; o > 0; o >>= 1) ss += __shfl_down_sync(0xffffffffu, ss, o);
    if ((t & 31) == 0) red[t >> 5] = ss;
    __syncthreads();
    __shared__ float s_inv;
    if (t == 0) {
        float tot = 0.f;
        #pragma unroll
        for (int w = 0; w < 16; w++) tot += red[w];
        s_inv = 1.0f / fmaxf(sqrtf(tot), 1e-12f);
    }
    __syncthreads();
    const float inv = s_inv;
    float4 q = make_float4(acc.x * inv, acc.y * inv, acc.z * inv, acc.w * inv);
    *(float4*)&g_q[b][d0] = q;
}

// ---------------------------------------------------------------------------
// Kernel 3: sims. 256 blocks x 512 threads (16 warps); 2 keys per warp.
// Same block count as R6 (no wave quantization), but 2x warps/SM -> ~28
// warps/SM to hide L2/HBM latency. Accumulators: dot[2][8]+ssq[2] = 18 regs.
// ---------------------------------------------------------------------------
__global__ void __launch_bounds__(512) k_sims(const float* __restrict__ keys) {
    extern __shared__ float sq[];  // [Bb][Dd] = 64KB
    for (int i = threadIdx.x; i < Bb * Dd / 4; i += blockDim.x)
        ((float4*)sq)[i] = ((const float4*)g_q)[i];
    __syncthreads();

    const int warp = threadIdx.x >> 5, lane = threadIdx.x & 31;
    const int n0 = (blockIdx.x * 16 + warp) * 2;   // 2 keys per warp

    const float4* __restrict__ k0 = (const float4*)(keys + (size_t)(n0 + 0) * Dd);
    const float4* __restrict__ k1 = (const float4*)(keys + (size_t)(n0 + 1) * Dd);

    float dot[2][Bb];
    float ssq[2] = {0.f, 0.f};
    #pragma unroll
    for (int j = 0; j < 2; j++)
        #pragma unroll
        for (int bb = 0; bb < Bb; bb++) dot[j][bb] = 0.f;

    #pragma unroll 2
    for (int i = lane; i < Dd / 4; i += 32) {
        float4 kv[2];
        kv[0] = __ldcs(&k0[i]);
        kv[1] = __ldcs(&k1[i]);
        #pragma unroll
        for (int j = 0; j < 2; j++)
            ssq[j] += kv[j].x * kv[j].x + kv[j].y * kv[j].y
                    + kv[j].z * kv[j].z + kv[j].w * kv[j].w;
        #pragma unroll
        for (int bb = 0; bb < Bb; bb++) {
            float4 qv = ((const float4*)(sq + bb * Dd))[i];
            #pragma unroll
            for (int j = 0; j < 2; j++)
                dot[j][bb] += kv[j].x * qv.x + kv[j].y * qv.y
                            + kv[j].z * qv.z + kv[j].w * qv.w;
        }
    }
    #pragma unroll
    for (int o = 16; o > 0; o >>= 1) {
        #pragma unroll
        for (int j = 0; j < 2; j++) {
            ssq[j] += __shfl_down_sync(0xffffffffu, ssq[j], o);
            #pragma unroll
            for (int bb = 0; bb < Bb; bb++)
                dot[j][bb] += __shfl_down_sync(0xffffffffu, dot[j][bb], o);
        }
    }
    if (lane == 0) {
        #pragma unroll
        for (int j = 0; j < 2; j++) {
            float inv = 1.0f / fmaxf(sqrtf(ssq[j]), 1e-12f);
            #pragma unroll
            for (int bb = 0; bb < Bb; bb++) g_sims[bb][n0 + j] = dot[j][bb] * inv;
        }
    }
}

// ---------------------------------------------------------------------------
// Kernel 4: fused select+gather. grid (8 col-chunks, Bb) x 1024 threads.
// (R14-proven WIN: redundant per-block select, per-block gather chunk)
// ---------------------------------------------------------------------------
__global__ void __launch_bounds__(1024) k_select_gather(
    const unsigned char* __restrict__ mask,
    const float* __restrict__ values, float* __restrict__ out) {
    const int c = blockIdx.x, b = blockIdx.y, t = threadIdx.x;
    const int w = t >> 5, lane = t & 31;

    __shared__ int      s_hist[256];
    __shared__ int      s_B, s_carried;
    __shared__ int      s_redc[32];
    __shared__ int      s_topi[KTOP];
    __shared__ int      s_eqi[KTOP];
    __shared__ int      s_ngt, s_neq;
    __shared__ unsigned s_umax;
    __shared__ float    s_w[KTOP];
    __shared__ int      s_last;
    __shared__ float4   sacc[16][64];   // 16KB gather partials

    // ---- mask count (last valid index) ----
    int cnt = 0;
    #pragma unroll
    for (int i = 0; i < 4; i++) cnt += (int)mask[b * Ss + t + i * 1024];
    for (int o = 16; o > 0; o >>= 1) cnt += __shfl_down_sync(0xffffffffu, cnt, o);
    if (lane == 0) s_redc[w] = cnt;

    // ---- load sims -> order-preserving uint ----
    unsigned u[8];
    #pragma unroll
    for (int j = 0; j < 8; j++) {
        unsigned bits = __float_as_uint(g_sims[b][t + j * 1024]);
        u[j] = bits ^ (unsigned)(((int)bits >> 31) | 0x80000000);
    }

    // ---- 4-level radix: find exact 64th-largest u ----
    unsigned prefix = 0;
    int carried = 0;
    #pragma unroll
    for (int l = 3; l >= 0; l--) {
        if (t < 256) s_hist[t] = 0;
        __syncthreads();
        #pragma unroll
        for (int j = 0; j < 8; j++) {
            unsigned hi = (l == 3) ? 0u : (u[j] >> ((l + 1) * 8));
            if (hi == prefix)
                atomicAdd(&s_hist[(u[j] >> (l * 8)) & 255], 1);
        }
        __syncthreads();
        if (t < 32) {
            int h[8], gs = 0;
            #pragma unroll
            for (int j = 0; j < 8; j++) { h[j] = s_hist[lane * 8 + j]; gs += h[j]; }
            int suf = gs;
            #pragma unroll
            for (int o = 1; o < 32; o <<= 1) {
                int v = __shfl_down_sync(0xffffffffu, suf, o);
                if (lane < 32 - o) suf += v;
            }
            int cum = carried + (suf - gs);
            #pragma unroll
            for (int j = 7; j >= 0; j--) {
                int before = cum;
                cum += h[j];
                if (before < KTOP && cum >= KTOP) { s_B = lane * 8 + j; s_carried = before; }
            }
        }
        __syncthreads();
        prefix = (prefix << 8) | (unsigned)s_B;
        carried = s_carried;
        __syncthreads();
    }
    const unsigned p = prefix;

    if (t == 0) { s_ngt = 0; s_neq = 0; s_umax = p; }
    __syncthreads();

    // ---- collect: all u > p, then fill with u == p ----
    unsigned local_max = 0;
    #pragma unroll
    for (int j = 0; j < 8; j++) {
        if (u[j] > p) {
            int pos = atomicAdd(&s_ngt, 1);
            s_topi[pos] = t + j * 1024;
            if (u[j] > local_max) local_max = u[j];
        } else if (u[j] == p) {
            int pos = atomicAdd(&s_neq, 1);
            if (pos < KTOP) s_eqi[pos] = t + j * 1024;
        }
    }
    if (local_max > p) atomicMax(&s_umax, local_max);
    __syncthreads();
    const int ngt = s_ngt;
    if (t < KTOP - ngt) s_topi[ngt + t] = s_eqi[t];

    const unsigned umax = s_umax;
    const unsigned mb = (umax >> 31) ? (umax ^ 0x80000000u) : ~umax;
    const float fmaxv = __uint_as_float(mb);
    __syncthreads();

    if (t < KTOP) s_w[t] = __expf((g_sims[b][s_topi[t]] - fmaxv) * (1.0f / 0.03f));
    __syncthreads();
    if (t == 0) {
        float sum = 0.f;
        #pragma unroll
        for (int k = 0; k < KTOP; k++) sum += s_w[k];
        float gate = 1.0f / (1.0f + __expf(-(fmaxv - 0.85f) * 40.0f));
        s_hist[0] = __float_as_int(16.0f * gate / sum);   // stash scale
        int tot = 0;
        #pragma unroll
        for (int ww = 0; ww < 32; ww++) tot += s_redc[ww];
        s_last = max(tot, 1) - 1;
    }
    __syncthreads();
    const float scale = __int_as_float(s_hist[0]);
    if (t < KTOP) s_w[t] *= scale;
    __syncthreads();

    // ---- gather this block's 256-float chunk: 16 k-groups x 64 cols ----
    const int col = t & 63;
    const int grp = t >> 6;
    const int doff = c * 256 + col * 4;

    float4 acc = make_float4(0.f, 0.f, 0.f, 0.f);
    #pragma unroll
    for (int kk = 0; kk < 4; kk++) {
        const int k = grp * 4 + kk;
        const float4 vv = __ldg((const float4*)(values + (size_t)s_topi[k] * Dd + doff));
        const float wk = s_w[k];
        acc.x += wk * vv.x; acc.y += wk * vv.y;
        acc.z += wk * vv.z; acc.w += wk * vv.w;
    }
    sacc[grp][col] = acc;
    __syncthreads();
    if (t < 64) {
        float4 a = sacc[0][t];
        #pragma unroll
        for (int g = 1; g < 16; g++) {
            float4 v = sacc[g][t];
            a.x += v.x; a.y += v.y; a.z += v.z; a.w += v.w;
        }
        float* op = out + (size_t)b * Ss * Dd + (size_t)s_last * Dd + c * 256 + t * 4;
        float4 cur = *(float4*)op;
        cur.x += a.x; cur.y += a.y; cur.z += a.z; cur.w += a.w;
        *(float4*)op = cur;
    }
}

extern "C" void kernel_launch(void* const* d_in, const int* in_sizes, int n_in,
                              void* d_out, int out_size) {
    const float*         x    = (const float*)d_in[0];
    const unsigned char* mask = (const unsigned char*)d_in[1];
    const float*         keys = (const float*)d_in[2];
    const float*         vals = (const float*)d_in[3];
    float* out = (float*)d_out;

    cudaFuncSetAttribute(k_sims, cudaFuncAttributeMaxDynamicSharedMemorySize,
                         Bb * Dd * (int)sizeof(float));

    k_copy_reduce<<<dim3(Dd / 1024, SCHUNKS, Bb), 256>>>(x, mask, out);
    k_qnorm<<<Bb, 512>>>();
    k_sims<<<256, 512, Bb * Dd * sizeof(float)>>>(keys);
    k_select_gather<<<dim3(8, Bb), 1024>>>(mask, vals, out);
}